// round 14
// baseline (speedup 1.0000x reference)
#include <cuda_runtime.h>
#include <math_constants.h>

#define NN   100000
#define EE   3200000
#define FIN  512
#define HID  16
#define NG   10
#define GF   160
#define LAMDA 0.001f
#define EPSN  1e-5f

#define SCAN_CHUNK 1024
#define NBLK ((NN + SCAN_CHUNK - 1) / SCAN_CHUNK)   // 98

// ---------------- device scratch ----------------
__device__ float  g_deg[NN];
__device__ int    g_cnt[NN];
__device__ int    g_rowstart[NN];
__device__ int    g_fill[NN];
__device__ int    g_bsum[NBLK];
__device__ int    g_csr_r[EE];
__device__ float  g_h  [NN * HID];
__device__ float  g_agg[NN * HID];
__device__ double g_sums[2 * GF];
__device__ float  g_rsg[GF];
__device__ float  g_cvec[HID];
__device__ int    g_ctr;
__device__ int    g_ctr2;
__device__ volatile int g_flag;

// ---------------- helpers: packed f32x2 ----------------
__device__ __forceinline__ unsigned long long pack2(float a) {
    unsigned int u = __float_as_uint(a);
    unsigned long long r;
    asm("mov.b64 %0, {%1, %1};" : "=l"(r) : "r"(u));
    return r;
}
__device__ __forceinline__ void fma2(unsigned long long& acc,
                                     unsigned long long a, unsigned long long b) {
    asm("fma.rn.f32x2 %0, %1, %2, %3;" : "=l"(acc) : "l"(a), "l"(b), "l"(acc));
}

// ---------------- CSR build ----------------
__global__ void zero_cnt_kernel() {
    int i = blockIdx.x * blockDim.x + threadIdx.x;
    if (i < NN) g_cnt[i] = 0;
}

__global__ void count_kernel(const int* __restrict__ ei) {
    int e = blockIdx.x * blockDim.x + threadIdx.x;
    if (e < EE) atomicAdd(&g_cnt[__ldg(&ei[EE + e])], 1);
}

// scan1 + fused dinv
__global__ __launch_bounds__(512) void scan1_kernel() {
    __shared__ int sh[512];
    int b = blockIdx.x, t = threadIdx.x;
    int i0 = b * SCAN_CHUNK + 2 * t;
    int c0 = (i0     < NN) ? g_cnt[i0]     : 0;
    int c1 = (i0 + 1 < NN) ? g_cnt[i0 + 1] : 0;
    if (i0     < NN) g_deg[i0]     = (c0 > 0) ? rsqrtf((float)c0) : 0.0f;
    if (i0 + 1 < NN) g_deg[i0 + 1] = (c1 > 0) ? rsqrtf((float)c1) : 0.0f;
    sh[t] = c0 + c1;
    __syncthreads();
    for (int off = 256; off > 0; off >>= 1) {
        if (t < off) sh[t] += sh[t + off];
        __syncthreads();
    }
    if (t == 0) g_bsum[b] = sh[0];
}

__global__ __launch_bounds__(512) void scan3_kernel() {
    __shared__ int sh[512];
    __shared__ int base_sh;
    int b = blockIdx.x, t = threadIdx.x;

    sh[t] = (t < b && t < NBLK) ? g_bsum[t] : 0;
    __syncthreads();
    for (int off = 256; off > 0; off >>= 1) {
        if (t < off) sh[t] += sh[t + off];
        __syncthreads();
    }
    if (t == 0) base_sh = sh[0];
    __syncthreads();
    int base = base_sh;
    __syncthreads();

    int i0 = b * SCAN_CHUNK + 2 * t;
    int c0 = (i0     < NN) ? g_cnt[i0]     : 0;
    int c1 = (i0 + 1 < NN) ? g_cnt[i0 + 1] : 0;
    int pair = c0 + c1;
    sh[t] = pair;
    __syncthreads();
    for (int off = 1; off < 512; off <<= 1) {
        int v = (t >= off) ? sh[t - off] : 0;
        __syncthreads();
        sh[t] += v;
        __syncthreads();
    }
    int ex = sh[t] - pair + base;
    if (i0 < NN) {
        g_rowstart[i0] = ex;
        g_fill[i0] = ex;
    }
    if (i0 + 1 < NN) {
        g_rowstart[i0 + 1] = ex + c0;
        g_fill[i0 + 1] = ex + c0;
    }
}

__global__ void fill_kernel(const int* __restrict__ ei) {
    int e = blockIdx.x * blockDim.x + threadIdx.x;
    if (e >= EE) return;
    int r = __ldg(&ei[e]);
    int c = __ldg(&ei[EE + e]);
    int pos = atomicAdd(&g_fill[c], 1);
    g_csr_r[pos] = r;
}

// ---------------- mm0: 256 thr x 1 node, 24 warps/SM, cp.async 2-stage ----------------
// MMB=256, grid 391, smem 64KB -> 3 blocks/SM (444 slots >= 391: single wave).
// launch_bounds(256,3): reg cap 85; live set ~70 (8 acc2 only).
#define MMB 256
#define MMG ((NN + MMB - 1) / MMB)      // 391
__global__ __launch_bounds__(256, 3) void mm0_kernel(const float* __restrict__ x,
                                                     const float* __restrict__ W) {
    __shared__ __align__(16) float Ws[FIN * HID];      // 32 KB
    __shared__ __align__(16) float xs[2][MMB * 16];    // 32 KB
    int tid = threadIdx.x;
    for (int i = tid; i < FIN * HID; i += 256) Ws[i] = W[i];

    int n0 = blockIdx.x * MMB;
    int lr = tid >> 2;          // 0..63: base row for cooperative load
    int cb = tid & 3;           // 16B block within 64B chunk-row

    auto issue_chunk = [&](int kc, int b) {
#pragma unroll
        for (int it = 0; it < 4; it++) {
            int r = it * 64 + lr;
            int gr = n0 + r;
            if (gr >= NN) gr = NN - 1;
            const float* src = &x[(size_t)gr * FIN + kc * 16 + cb * 4];
            int blk = cb ^ ((r >> 1) & 3);
            unsigned sdst = (unsigned)__cvta_generic_to_shared(&xs[b][r * 16 + blk * 4]);
            asm volatile("cp.async.cg.shared.global [%0], [%1], 16;"
                         :: "r"(sdst), "l"(src));
        }
        asm volatile("cp.async.commit_group;");
    };

    issue_chunk(0, 0);
    issue_chunk(1, 1);

    unsigned long long acc2[8];
#pragma unroll
    for (int p = 0; p < 8; p++) acc2[p] = 0ull;

    int r0 = tid;               // compute row
    int key = (tid >> 1) & 3;

    for (int kc = 0; kc < FIN / 16; kc++) {
        if (kc < FIN / 16 - 1)
            asm volatile("cp.async.wait_group 1;");
        else
            asm volatile("cp.async.wait_group 0;");
        __syncthreads();

        const float4* base = (const float4*)&xs[kc & 1][0];
#pragma unroll
        for (int c = 0; c < 4; c++) {
            float4 va = base[r0 * 4 + (c ^ key)];
            float xa[4] = {va.x, va.y, va.z, va.w};
#pragma unroll
            for (int kk = 0; kk < 4; kk++) {
                int k = kc * 16 + c * 4 + kk;
                const ulonglong2* wp = (const ulonglong2*)&Ws[k * HID];
                ulonglong2 w01 = wp[0], w23 = wp[1], w45 = wp[2], w67 = wp[3];
                unsigned long long xp = pack2(xa[kk]);
                fma2(acc2[0], xp, w01.x); fma2(acc2[1], xp, w01.y);
                fma2(acc2[2], xp, w23.x); fma2(acc2[3], xp, w23.y);
                fma2(acc2[4], xp, w45.x); fma2(acc2[5], xp, w45.y);
                fma2(acc2[6], xp, w67.x); fma2(acc2[7], xp, w67.y);
            }
        }
        __syncthreads();
        if (kc + 2 < FIN / 16) issue_chunk(kc + 2, kc & 1);
    }

    int n = n0 + r0;
    if (n < NN) {
        float dv = g_deg[n];
        union { unsigned long long u; float2 f; } cv;
        float4* o = (float4*)&g_h[(size_t)n * HID];
#pragma unroll
        for (int q = 0; q < 4; q++) {
            float4 rr;
            cv.u = acc2[2 * q];     rr.x = cv.f.x * dv; rr.y = cv.f.y * dv;
            cv.u = acc2[2 * q + 1]; rr.z = cv.f.x * dv; rr.w = cv.f.y * dv;
            o[q] = rr;
        }
    }
}

// ---------------- gather: warp per node, 4 lanes/edge, 2-way unroll (proven) ----------------
__global__ __launch_bounds__(256) void gather_kernel() {
    int node = blockIdx.x * 8 + (threadIdx.x >> 5);
    if (node >= NN) return;
    int lane = threadIdx.x & 31;
    int p = lane & 3;

    int s = g_rowstart[node];
    int e = s + g_cnt[node];
    int j = s + (lane >> 2);

    float4 a0 = make_float4(0.f, 0.f, 0.f, 0.f);
    float4 a1 = make_float4(0.f, 0.f, 0.f, 0.f);
    const float4* h4 = (const float4*)g_h;

    while (j < e - 8) {
        int r0 = __ldg(&g_csr_r[j]);
        int r1 = __ldg(&g_csr_r[j + 8]);
        float4 v0 = __ldg(&h4[(size_t)r0 * 4 + p]);
        float4 v1 = __ldg(&h4[(size_t)r1 * 4 + p]);
        a0.x += v0.x; a0.y += v0.y; a0.z += v0.z; a0.w += v0.w;
        a1.x += v1.x; a1.y += v1.y; a1.z += v1.z; a1.w += v1.w;
        j += 16;
    }
    if (j < e) {
        int r0 = __ldg(&g_csr_r[j]);
        float4 v0 = __ldg(&h4[(size_t)r0 * 4 + p]);
        a0.x += v0.x; a0.y += v0.y; a0.z += v0.z; a0.w += v0.w;
    }
    a0.x += a1.x; a0.y += a1.y; a0.z += a1.z; a0.w += a1.w;

#pragma unroll
    for (int m = 16; m >= 4; m >>= 1) {
        a0.x += __shfl_xor_sync(0xffffffff, a0.x, m);
        a0.y += __shfl_xor_sync(0xffffffff, a0.y, m);
        a0.z += __shfl_xor_sync(0xffffffff, a0.z, m);
        a0.w += __shfl_xor_sync(0xffffffff, a0.w, m);
    }
    if (lane < 4) {
        float dc = g_deg[node];
        a0.x *= dc; a0.y *= dc; a0.z *= dc; a0.w *= dc;
        ((float4*)g_agg)[(size_t)node * 4 + lane] = a0;
    }
}

// ---------------- fused stats + grid-sync + apply (+mm16 / out) ----------------
__global__ __launch_bounds__(256, 3) void statsapply_kernel(
    const float* __restrict__ L, const float* __restrict__ gamma,
    const float* __restrict__ beta, const float* __restrict__ Wn,
    float* __restrict__ out, int epoch, int isfinal)
{
    __shared__ float Ls[HID * NG];
    __shared__ float xs[256 * HID];
    __shared__ float ss[256 * NG];
    __shared__ float tsh[GF];
    __shared__ float rgS[GF];
    __shared__ float csS[HID];
    __shared__ float WsS[HID * HID];
    __shared__ int is_last;
    int tid = threadIdx.x;
    if (tid < HID * NG) Ls[tid] = L[tid];
    __syncthreads();

    int nIdx = blockIdx.x * 256 + tid;
    float xr[HID];
    float sv[NG];
#pragma unroll
    for (int k = 0; k < HID; k++) xr[k] = 0.0f;
#pragma unroll
    for (int g = 0; g < NG; g++) sv[g] = 0.0f;

    if (nIdx < NN) {
        const float4* xi = (const float4*)&g_agg[(size_t)nIdx * HID];
#pragma unroll
        for (int q = 0; q < 4; q++) {
            float4 v = xi[q];
            xr[q * 4 + 0] = v.x; xr[q * 4 + 1] = v.y; xr[q * 4 + 2] = v.z; xr[q * 4 + 3] = v.w;
        }
        float logit[NG];
#pragma unroll
        for (int g = 0; g < NG; g++) logit[g] = 0.0f;
#pragma unroll
        for (int k = 0; k < HID; k++)
#pragma unroll
            for (int g = 0; g < NG; g++) logit[g] += xr[k] * Ls[k * NG + g];
        float m = -CUDART_INF_F;
#pragma unroll
        for (int g = 0; g < NG; g++) m = fmaxf(m, logit[g]);
        float sum = 0.0f;
#pragma unroll
        for (int g = 0; g < NG; g++) { sv[g] = __expf(logit[g] - m); sum += sv[g]; }
        float inv = 1.0f / sum;
#pragma unroll
        for (int g = 0; g < NG; g++) sv[g] *= inv;
    }

    {
        float4* xw = (float4*)&xs[tid * HID];
#pragma unroll
        for (int q = 0; q < 4; q++)
            xw[q] = make_float4(xr[q * 4 + 0], xr[q * 4 + 1], xr[q * 4 + 2], xr[q * 4 + 3]);
#pragma unroll
        for (int g = 0; g < NG; g++) ss[tid * NG + g] = sv[g];
    }
    __syncthreads();

    if (tid < GF) {
        int g = tid >> 4;
        int f = tid & 15;
        float a1 = 0.0f, a2 = 0.0f;
        for (int jj = 0; jj < 256; jj++) {
            float t = ss[jj * NG + g] * xs[jj * HID + f];
            a1 += t;
            a2 += t * t;
        }
        atomicAdd(&g_sums[tid], (double)a1);
        atomicAdd(&g_sums[GF + tid], (double)a2);
    }

    __threadfence();
    if (tid == 0) {
        int old = atomicAdd(&g_ctr, 1);
        is_last = (old == (int)gridDim.x - 1) ? 1 : 0;
    }
    __syncthreads();
    if (is_last) {
        if (tid < GF) {
            double s1 = g_sums[tid];
            double s2 = g_sums[GF + tid];
            g_sums[tid] = 0.0;
            g_sums[GF + tid] = 0.0;
            double mean = s1 / (double)NN;
            double var  = s2 / (double)NN - mean * mean;
            float v = (float)var;
            if (v < 0.0f) v = 0.0f;
            float rs = rsqrtf(v + EPSN);
            float rg = rs * gamma[tid];
            g_rsg[tid] = rg;
            tsh[tid] = beta[tid] - (float)mean * rg;
        }
        __syncthreads();
        if (tid < HID) {
            float cf = 0.0f;
#pragma unroll
            for (int g = 0; g < NG; g++) cf += tsh[g * HID + tid];
            g_cvec[tid] = cf;
        }
        if (tid == 0) g_ctr = 0;
        __syncthreads();
        if (tid == 0) {
            __threadfence();
            atomicExch((int*)&g_flag, epoch);
        }
    }

    if (tid == 0) {
        while (atomicAdd((int*)&g_flag, 0) != epoch) __nanosleep(64);
    }
    __syncthreads();

    if (tid < GF) rgS[tid] = __ldcg(&g_rsg[tid]);
    if (tid < HID) csS[tid] = __ldcg(&g_cvec[tid]);
    if (!isfinal && tid < HID * HID) WsS[tid] = Wn[tid];
    __syncthreads();

    if (nIdx < NN) {
        float res[HID];
#pragma unroll
        for (int f = 0; f < HID; f++) {
            float a = 0.0f;
#pragma unroll
            for (int g = 0; g < NG; g++) a += sv[g] * rgS[g * HID + f];
            float v = xr[f] + LAMDA * (xr[f] * a + csS[f]);
            res[f] = fmaxf(v, 0.0f);
        }

        if (isfinal) {
            float4* o = (float4*)&out[(size_t)nIdx * HID];
#pragma unroll
            for (int q = 0; q < 4; q++)
                o[q] = make_float4(res[q * 4 + 0], res[q * 4 + 1],
                                   res[q * 4 + 2], res[q * 4 + 3]);
        } else {
            float acc[HID];
#pragma unroll
            for (int f = 0; f < HID; f++) acc[f] = 0.0f;
#pragma unroll
            for (int k = 0; k < HID; k++)
#pragma unroll
                for (int f = 0; f < HID; f++) acc[f] += res[k] * WsS[k * HID + f];
            float dv = g_deg[nIdx];
            float4* o = (float4*)&g_h[(size_t)nIdx * HID];
#pragma unroll
            for (int q = 0; q < 4; q++)
                o[q] = make_float4(acc[q * 4 + 0] * dv, acc[q * 4 + 1] * dv,
                                   acc[q * 4 + 2] * dv, acc[q * 4 + 3] * dv);
        }
    }

    __threadfence();
    if (tid == 0) {
        int old = atomicAdd(&g_ctr2, 1);
        if (old == (int)gridDim.x - 1) {
            g_ctr2 = 0;
            atomicExch((int*)&g_flag, 0);
        }
    }
}

// ---------------- launcher ----------------
extern "C" void kernel_launch(void* const* d_in, const int* in_sizes, int n_in,
                              void* d_out, int out_size) {
    const float* x  = (const float*)d_in[0];
    const int*   ei = (const int*)d_in[1];
    const float* W[3] = {(const float*)d_in[2], (const float*)d_in[3], (const float*)d_in[4]};
    const float* L[3] = {(const float*)d_in[5], (const float*)d_in[6], (const float*)d_in[7]};
    const float* gm[3] = {(const float*)d_in[8], (const float*)d_in[9], (const float*)d_in[10]};
    const float* bt[3] = {(const float*)d_in[11], (const float*)d_in[12], (const float*)d_in[13]};
    float* out = (float*)d_out;

    const int TB = 256;
    zero_cnt_kernel<<<(NN + TB - 1) / TB, TB>>>();        // 1
    count_kernel<<<(EE + TB - 1) / TB, TB>>>(ei);         // 2
    scan1_kernel<<<NBLK, 512>>>();                        // 3 (+dinv fused)
    mm0_kernel<<<MMG, 256>>>(x, W[0]);                    // 4  <- profiled slot
    scan3_kernel<<<NBLK, 512>>>();                        // 5
    fill_kernel<<<(EE + TB - 1) / TB, TB>>>(ei);          // 6

    for (int i = 0; i < 3; i++) {
        gather_kernel<<<(NN + 7) / 8, 256>>>();
        statsapply_kernel<<<(NN + 255) / 256, 256>>>(
            L[i], gm[i], bt[i], i < 2 ? W[i + 1] : W[0], out, i + 1, i == 2 ? 1 : 0);
    }
}

// round 15
// speedup vs baseline: 1.0739x; 1.0739x over previous
#include <cuda_runtime.h>
#include <math_constants.h>

#define NN   100000
#define EE   3200000
#define FIN  512
#define HID  16
#define NG   10
#define GF   160
#define LAMDA 0.001f
#define EPSN  1e-5f

#define SCAN_CHUNK 1024
#define NBLK ((NN + SCAN_CHUNK - 1) / SCAN_CHUNK)   // 98

// ---------------- device scratch ----------------
__device__ float  g_deg[NN];
__device__ int    g_cnt[NN];          // zero at load; re-zeroed by final statsapply
__device__ int    g_rowstart[NN];
__device__ int    g_fill[NN];
__device__ int    g_bsum[NBLK];
__device__ int    g_csr_r[EE];
__device__ float  g_h  [NN * HID];
__device__ float  g_agg[NN * HID];
__device__ double g_sums[2 * GF];
__device__ float  g_rsg[GF];
__device__ float  g_cvec[HID];
__device__ int    g_ctr;
__device__ int    g_ctr2;
__device__ volatile int g_flag;

// ---------------- helpers: packed f32x2 ----------------
__device__ __forceinline__ unsigned long long pack2(float a) {
    unsigned int u = __float_as_uint(a);
    unsigned long long r;
    asm("mov.b64 %0, {%1, %1};" : "=l"(r) : "r"(u));
    return r;
}
__device__ __forceinline__ void fma2(unsigned long long& acc,
                                     unsigned long long a, unsigned long long b) {
    asm("fma.rn.f32x2 %0, %1, %2, %3;" : "=l"(acc) : "l"(a), "l"(b), "l"(acc));
}

// ---------------- CSR build ----------------
__global__ void count_kernel(const int* __restrict__ ei) {
    int e = blockIdx.x * blockDim.x + threadIdx.x;
    if (e < EE) atomicAdd(&g_cnt[__ldg(&ei[EE + e])], 1);
}

// scan1 + fused dinv
__global__ __launch_bounds__(512) void scan1_kernel() {
    __shared__ int sh[512];
    int b = blockIdx.x, t = threadIdx.x;
    int i0 = b * SCAN_CHUNK + 2 * t;
    int c0 = (i0     < NN) ? g_cnt[i0]     : 0;
    int c1 = (i0 + 1 < NN) ? g_cnt[i0 + 1] : 0;
    if (i0     < NN) g_deg[i0]     = (c0 > 0) ? rsqrtf((float)c0) : 0.0f;
    if (i0 + 1 < NN) g_deg[i0 + 1] = (c1 > 0) ? rsqrtf((float)c1) : 0.0f;
    sh[t] = c0 + c1;
    __syncthreads();
    for (int off = 256; off > 0; off >>= 1) {
        if (t < off) sh[t] += sh[t + off];
        __syncthreads();
    }
    if (t == 0) g_bsum[b] = sh[0];
}

__global__ __launch_bounds__(512) void scan3_kernel() {
    __shared__ int sh[512];
    __shared__ int base_sh;
    int b = blockIdx.x, t = threadIdx.x;

    sh[t] = (t < b && t < NBLK) ? g_bsum[t] : 0;
    __syncthreads();
    for (int off = 256; off > 0; off >>= 1) {
        if (t < off) sh[t] += sh[t + off];
        __syncthreads();
    }
    if (t == 0) base_sh = sh[0];
    __syncthreads();
    int base = base_sh;
    __syncthreads();

    int i0 = b * SCAN_CHUNK + 2 * t;
    int c0 = (i0     < NN) ? g_cnt[i0]     : 0;
    int c1 = (i0 + 1 < NN) ? g_cnt[i0 + 1] : 0;
    int pair = c0 + c1;
    sh[t] = pair;
    __syncthreads();
    for (int off = 1; off < 512; off <<= 1) {
        int v = (t >= off) ? sh[t - off] : 0;
        __syncthreads();
        sh[t] += v;
        __syncthreads();
    }
    int ex = sh[t] - pair + base;
    if (i0 < NN) {
        g_rowstart[i0] = ex;
        g_fill[i0] = ex;
    }
    if (i0 + 1 < NN) {
        g_rowstart[i0 + 1] = ex + c0;
        g_fill[i0 + 1] = ex + c0;
    }
}

__global__ void fill_kernel(const int* __restrict__ ei) {
    int e = blockIdx.x * blockDim.x + threadIdx.x;
    if (e >= EE) return;
    int r = __ldg(&ei[e]);
    int c = __ldg(&ei[EE + e]);
    int pos = atomicAdd(&g_fill[c], 1);
    g_csr_r[pos] = r;
}

// ---------------- mm0: proven R13 version (2 nodes/thread, 128thr, 3 blocks/SM) ----------------
#define MMB 256
#define MMG ((NN + MMB - 1) / MMB)      // 391
__global__ __launch_bounds__(128, 3) void mm0_kernel(const float* __restrict__ x,
                                                     const float* __restrict__ W) {
    __shared__ __align__(16) float Ws[FIN * HID];      // 32 KB
    __shared__ __align__(16) float xs[2][MMB * 16];    // 32 KB
    int tid = threadIdx.x;
    for (int i = tid; i < FIN * HID; i += 128) Ws[i] = W[i];

    int n0 = blockIdx.x * MMB;
    int lr = tid >> 2;
    int cb = tid & 3;

    auto issue_chunk = [&](int kc, int b) {
#pragma unroll
        for (int it = 0; it < 8; it++) {
            int r = it * 32 + lr;
            int gr = n0 + r;
            if (gr >= NN) gr = NN - 1;
            const float* src = &x[(size_t)gr * FIN + kc * 16 + cb * 4];
            int blk = cb ^ ((r >> 1) & 3);
            unsigned sdst = (unsigned)__cvta_generic_to_shared(&xs[b][r * 16 + blk * 4]);
            asm volatile("cp.async.cg.shared.global [%0], [%1], 16;"
                         :: "r"(sdst), "l"(src));
        }
        asm volatile("cp.async.commit_group;");
    };

    issue_chunk(0, 0);
    issue_chunk(1, 1);

    unsigned long long accA[8], accB[8];
#pragma unroll
    for (int p = 0; p < 8; p++) { accA[p] = 0ull; accB[p] = 0ull; }

    int r0 = tid;
    int r1 = tid + 128;
    int key = (tid >> 1) & 3;

    for (int kc = 0; kc < FIN / 16; kc++) {
        if (kc < FIN / 16 - 1)
            asm volatile("cp.async.wait_group 1;");
        else
            asm volatile("cp.async.wait_group 0;");
        __syncthreads();

        const float4* base = (const float4*)&xs[kc & 1][0];
#pragma unroll
        for (int c = 0; c < 4; c++) {
            float4 va = base[r0 * 4 + (c ^ key)];
            float4 vb = base[r1 * 4 + (c ^ key)];
            float xa[4] = {va.x, va.y, va.z, va.w};
            float xb[4] = {vb.x, vb.y, vb.z, vb.w};
#pragma unroll
            for (int kk = 0; kk < 4; kk++) {
                int k = kc * 16 + c * 4 + kk;
                const ulonglong2* wp = (const ulonglong2*)&Ws[k * HID];
                ulonglong2 w01 = wp[0], w23 = wp[1], w45 = wp[2], w67 = wp[3];
                unsigned long long xpA = pack2(xa[kk]);
                unsigned long long xpB = pack2(xb[kk]);
                fma2(accA[0], xpA, w01.x); fma2(accA[1], xpA, w01.y);
                fma2(accA[2], xpA, w23.x); fma2(accA[3], xpA, w23.y);
                fma2(accA[4], xpA, w45.x); fma2(accA[5], xpA, w45.y);
                fma2(accA[6], xpA, w67.x); fma2(accA[7], xpA, w67.y);
                fma2(accB[0], xpB, w01.x); fma2(accB[1], xpB, w01.y);
                fma2(accB[2], xpB, w23.x); fma2(accB[3], xpB, w23.y);
                fma2(accB[4], xpB, w45.x); fma2(accB[5], xpB, w45.y);
                fma2(accB[6], xpB, w67.x); fma2(accB[7], xpB, w67.y);
            }
        }
        __syncthreads();
        if (kc + 2 < FIN / 16) issue_chunk(kc + 2, kc & 1);
    }

    union { unsigned long long u; float2 f; } cv;
    int nA = n0 + r0;
    if (nA < NN) {
        float dv = g_deg[nA];
        float4* o = (float4*)&g_h[(size_t)nA * HID];
#pragma unroll
        for (int q = 0; q < 4; q++) {
            float4 rr;
            cv.u = accA[2 * q];     rr.x = cv.f.x * dv; rr.y = cv.f.y * dv;
            cv.u = accA[2 * q + 1]; rr.z = cv.f.x * dv; rr.w = cv.f.y * dv;
            o[q] = rr;
        }
    }
    int nB = n0 + r1;
    if (nB < NN) {
        float dv = g_deg[nB];
        float4* o = (float4*)&g_h[(size_t)nB * HID];
#pragma unroll
        for (int q = 0; q < 4; q++) {
            float4 rr;
            cv.u = accB[2 * q];     rr.x = cv.f.x * dv; rr.y = cv.f.y * dv;
            cv.u = accB[2 * q + 1]; rr.z = cv.f.x * dv; rr.w = cv.f.y * dv;
            o[q] = rr;
        }
    }
}

// ---------------- gather: warp per node, 4 lanes/edge, 2-way unroll (proven) ----------------
__global__ __launch_bounds__(256) void gather_kernel() {
    int node = blockIdx.x * 8 + (threadIdx.x >> 5);
    if (node >= NN) return;
    int lane = threadIdx.x & 31;
    int p = lane & 3;

    int s = g_rowstart[node];
    int e = s + g_cnt[node];
    int j = s + (lane >> 2);

    float4 a0 = make_float4(0.f, 0.f, 0.f, 0.f);
    float4 a1 = make_float4(0.f, 0.f, 0.f, 0.f);
    const float4* h4 = (const float4*)g_h;

    while (j < e - 8) {
        int r0 = __ldg(&g_csr_r[j]);
        int r1 = __ldg(&g_csr_r[j + 8]);
        float4 v0 = __ldg(&h4[(size_t)r0 * 4 + p]);
        float4 v1 = __ldg(&h4[(size_t)r1 * 4 + p]);
        a0.x += v0.x; a0.y += v0.y; a0.z += v0.z; a0.w += v0.w;
        a1.x += v1.x; a1.y += v1.y; a1.z += v1.z; a1.w += v1.w;
        j += 16;
    }
    if (j < e) {
        int r0 = __ldg(&g_csr_r[j]);
        float4 v0 = __ldg(&h4[(size_t)r0 * 4 + p]);
        a0.x += v0.x; a0.y += v0.y; a0.z += v0.z; a0.w += v0.w;
    }
    a0.x += a1.x; a0.y += a1.y; a0.z += a1.z; a0.w += a1.w;

#pragma unroll
    for (int m = 16; m >= 4; m >>= 1) {
        a0.x += __shfl_xor_sync(0xffffffff, a0.x, m);
        a0.y += __shfl_xor_sync(0xffffffff, a0.y, m);
        a0.z += __shfl_xor_sync(0xffffffff, a0.z, m);
        a0.w += __shfl_xor_sync(0xffffffff, a0.w, m);
    }
    if (lane < 4) {
        float dc = g_deg[node];
        a0.x *= dc; a0.y *= dc; a0.z *= dc; a0.w *= dc;
        ((float4*)g_agg)[(size_t)node * 4 + lane] = a0;
    }
}

// ---------------- fused stats + grid-sync + apply (+mm16 / out) ----------------
__global__ __launch_bounds__(256, 3) void statsapply_kernel(
    const float* __restrict__ L, const float* __restrict__ gamma,
    const float* __restrict__ beta, const float* __restrict__ Wn,
    float* __restrict__ out, int epoch, int isfinal)
{
    __shared__ float Ls[HID * NG];
    __shared__ float xs[256 * HID];
    __shared__ float ss[256 * NG];
    __shared__ float tsh[GF];
    __shared__ float rgS[GF];
    __shared__ float csS[HID];
    __shared__ float WsS[HID * HID];
    __shared__ int is_last;
    int tid = threadIdx.x;
    if (tid < HID * NG) Ls[tid] = L[tid];
    __syncthreads();

    int nIdx = blockIdx.x * 256 + tid;
    float xr[HID];
    float sv[NG];
#pragma unroll
    for (int k = 0; k < HID; k++) xr[k] = 0.0f;
#pragma unroll
    for (int g = 0; g < NG; g++) sv[g] = 0.0f;

    if (nIdx < NN) {
        const float4* xi = (const float4*)&g_agg[(size_t)nIdx * HID];
#pragma unroll
        for (int q = 0; q < 4; q++) {
            float4 v = xi[q];
            xr[q * 4 + 0] = v.x; xr[q * 4 + 1] = v.y; xr[q * 4 + 2] = v.z; xr[q * 4 + 3] = v.w;
        }
        float logit[NG];
#pragma unroll
        for (int g = 0; g < NG; g++) logit[g] = 0.0f;
#pragma unroll
        for (int k = 0; k < HID; k++)
#pragma unroll
            for (int g = 0; g < NG; g++) logit[g] += xr[k] * Ls[k * NG + g];
        float m = -CUDART_INF_F;
#pragma unroll
        for (int g = 0; g < NG; g++) m = fmaxf(m, logit[g]);
        float sum = 0.0f;
#pragma unroll
        for (int g = 0; g < NG; g++) { sv[g] = __expf(logit[g] - m); sum += sv[g]; }
        float inv = 1.0f / sum;
#pragma unroll
        for (int g = 0; g < NG; g++) sv[g] *= inv;
    }

    {
        float4* xw = (float4*)&xs[tid * HID];
#pragma unroll
        for (int q = 0; q < 4; q++)
            xw[q] = make_float4(xr[q * 4 + 0], xr[q * 4 + 1], xr[q * 4 + 2], xr[q * 4 + 3]);
#pragma unroll
        for (int g = 0; g < NG; g++) ss[tid * NG + g] = sv[g];
    }
    __syncthreads();

    if (tid < GF) {
        int g = tid >> 4;
        int f = tid & 15;
        float a1 = 0.0f, a2 = 0.0f;
        for (int jj = 0; jj < 256; jj++) {
            float t = ss[jj * NG + g] * xs[jj * HID + f];
            a1 += t;
            a2 += t * t;
        }
        atomicAdd(&g_sums[tid], (double)a1);
        atomicAdd(&g_sums[GF + tid], (double)a2);
    }

    __threadfence();
    if (tid == 0) {
        int old = atomicAdd(&g_ctr, 1);
        is_last = (old == (int)gridDim.x - 1) ? 1 : 0;
    }
    __syncthreads();
    if (is_last) {
        if (tid < GF) {
            double s1 = g_sums[tid];
            double s2 = g_sums[GF + tid];
            g_sums[tid] = 0.0;
            g_sums[GF + tid] = 0.0;
            double mean = s1 / (double)NN;
            double var  = s2 / (double)NN - mean * mean;
            float v = (float)var;
            if (v < 0.0f) v = 0.0f;
            float rs = rsqrtf(v + EPSN);
            float rg = rs * gamma[tid];
            g_rsg[tid] = rg;
            tsh[tid] = beta[tid] - (float)mean * rg;
        }
        __syncthreads();
        if (tid < HID) {
            float cf = 0.0f;
#pragma unroll
            for (int g = 0; g < NG; g++) cf += tsh[g * HID + tid];
            g_cvec[tid] = cf;
        }
        if (tid == 0) g_ctr = 0;
        __syncthreads();
        if (tid == 0) {
            __threadfence();
            atomicExch((int*)&g_flag, epoch);
        }
    }

    if (tid == 0) {
        while (atomicAdd((int*)&g_flag, 0) != epoch) __nanosleep(64);
    }
    __syncthreads();

    if (tid < GF) rgS[tid] = __ldcg(&g_rsg[tid]);
    if (tid < HID) csS[tid] = __ldcg(&g_cvec[tid]);
    if (!isfinal && tid < HID * HID) WsS[tid] = Wn[tid];
    __syncthreads();

    if (nIdx < NN) {
        float res[HID];
#pragma unroll
        for (int f = 0; f < HID; f++) {
            float a = 0.0f;
#pragma unroll
            for (int g = 0; g < NG; g++) a += sv[g] * rgS[g * HID + f];
            float v = xr[f] + LAMDA * (xr[f] * a + csS[f]);
            res[f] = fmaxf(v, 0.0f);
        }

        if (isfinal) {
            float4* o = (float4*)&out[(size_t)nIdx * HID];
#pragma unroll
            for (int q = 0; q < 4; q++)
                o[q] = make_float4(res[q * 4 + 0], res[q * 4 + 1],
                                   res[q * 4 + 2], res[q * 4 + 3]);
        } else {
            float acc[HID];
#pragma unroll
            for (int f = 0; f < HID; f++) acc[f] = 0.0f;
#pragma unroll
            for (int k = 0; k < HID; k++)
#pragma unroll
                for (int f = 0; f < HID; f++) acc[f] += res[k] * WsS[k * HID + f];
            float dv = g_deg[nIdx];
            float4* o = (float4*)&g_h[(size_t)nIdx * HID];
#pragma unroll
            for (int q = 0; q < 4; q++)
                o[q] = make_float4(acc[q * 4 + 0] * dv, acc[q * 4 + 1] * dv,
                                   acc[q * 4 + 2] * dv, acc[q * 4 + 3] * dv);
        }
    }

    // final layer: re-zero g_cnt for the next invocation / graph replay
    if (isfinal && nIdx < NN) g_cnt[nIdx] = 0;

    __threadfence();
    if (tid == 0) {
        int old = atomicAdd(&g_ctr2, 1);
        if (old == (int)gridDim.x - 1) {
            g_ctr2 = 0;
            atomicExch((int*)&g_flag, 0);
        }
    }
}

// ---------------- launcher ----------------
extern "C" void kernel_launch(void* const* d_in, const int* in_sizes, int n_in,
                              void* d_out, int out_size) {
    const float* x  = (const float*)d_in[0];
    const int*   ei = (const int*)d_in[1];
    const float* W[3] = {(const float*)d_in[2], (const float*)d_in[3], (const float*)d_in[4]};
    const float* L[3] = {(const float*)d_in[5], (const float*)d_in[6], (const float*)d_in[7]};
    const float* gm[3] = {(const float*)d_in[8], (const float*)d_in[9], (const float*)d_in[10]};
    const float* bt[3] = {(const float*)d_in[11], (const float*)d_in[12], (const float*)d_in[13]};
    float* out = (float*)d_out;

    const int TB = 256;
    count_kernel<<<(EE + TB - 1) / TB, TB>>>(ei);         // 1
    scan1_kernel<<<NBLK, 512>>>();                        // 2 (+dinv fused)
    mm0_kernel<<<MMG, 128>>>(x, W[0]);                    // 3
    scan3_kernel<<<NBLK, 512>>>();                        // 4
    fill_kernel<<<(EE + TB - 1) / TB, TB>>>(ei);          // 5

    for (int i = 0; i < 3; i++) {
        gather_kernel<<<(NN + 7) / 8, 256>>>();
        statsapply_kernel<<<(NN + 255) / 256, 256>>>(
            L[i], gm[i], bt[i], i < 2 ? W[i + 1] : W[0], out, i + 1, i == 2 ? 1 : 0);
    }
}

// round 16
// speedup vs baseline: 1.1200x; 1.0429x over previous
#include <cuda_runtime.h>
#include <cuda_fp16.h>
#include <math_constants.h>

#define NN   100000
#define EE   3200000
#define FIN  512
#define HID  16
#define NG   10
#define GF   160
#define LAMDA 0.001f
#define EPSN  1e-5f

#define SCAN_CHUNK 1024
#define NBLK ((NN + SCAN_CHUNK - 1) / SCAN_CHUNK)   // 98

// ---------------- device scratch ----------------
__device__ float  g_deg[NN];
__device__ int    g_cnt[NN];          // zero at load; re-zeroed by final statsapply
__device__ int    g_rowstart[NN];
__device__ int    g_fill[NN];
__device__ int    g_bsum[NBLK];
__device__ int    g_csr_r[EE];
__device__ uint4  g_h[NN * 2];        // fp16 h: 16 halves = 32B = 2 uint4 per node
__device__ float  g_agg[NN * HID];
__device__ double g_sums[2 * GF];
__device__ float  g_rsg[GF];
__device__ float  g_cvec[HID];
__device__ int    g_ctr;
__device__ int    g_ctr2;
__device__ volatile int g_flag;

// ---------------- helpers: packed f32x2 ----------------
__device__ __forceinline__ unsigned long long pack2(float a) {
    unsigned int u = __float_as_uint(a);
    unsigned long long r;
    asm("mov.b64 %0, {%1, %1};" : "=l"(r) : "r"(u));
    return r;
}
__device__ __forceinline__ void fma2(unsigned long long& acc,
                                     unsigned long long a, unsigned long long b) {
    asm("fma.rn.f32x2 %0, %1, %2, %3;" : "=l"(acc) : "l"(a), "l"(b), "l"(acc));
}

// ---------------- CSR build ----------------
__global__ void count_kernel(const int* __restrict__ ei) {
    int e = blockIdx.x * blockDim.x + threadIdx.x;
    if (e < EE) atomicAdd(&g_cnt[__ldg(&ei[EE + e])], 1);
}

// scan1 + fused dinv
__global__ __launch_bounds__(512) void scan1_kernel() {
    __shared__ int sh[512];
    int b = blockIdx.x, t = threadIdx.x;
    int i0 = b * SCAN_CHUNK + 2 * t;
    int c0 = (i0     < NN) ? g_cnt[i0]     : 0;
    int c1 = (i0 + 1 < NN) ? g_cnt[i0 + 1] : 0;
    if (i0     < NN) g_deg[i0]     = (c0 > 0) ? rsqrtf((float)c0) : 0.0f;
    if (i0 + 1 < NN) g_deg[i0 + 1] = (c1 > 0) ? rsqrtf((float)c1) : 0.0f;
    sh[t] = c0 + c1;
    __syncthreads();
    for (int off = 256; off > 0; off >>= 1) {
        if (t < off) sh[t] += sh[t + off];
        __syncthreads();
    }
    if (t == 0) g_bsum[b] = sh[0];
}

__global__ __launch_bounds__(512) void scan3_kernel() {
    __shared__ int sh[512];
    __shared__ int base_sh;
    int b = blockIdx.x, t = threadIdx.x;

    sh[t] = (t < b && t < NBLK) ? g_bsum[t] : 0;
    __syncthreads();
    for (int off = 256; off > 0; off >>= 1) {
        if (t < off) sh[t] += sh[t + off];
        __syncthreads();
    }
    if (t == 0) base_sh = sh[0];
    __syncthreads();
    int base = base_sh;
    __syncthreads();

    int i0 = b * SCAN_CHUNK + 2 * t;
    int c0 = (i0     < NN) ? g_cnt[i0]     : 0;
    int c1 = (i0 + 1 < NN) ? g_cnt[i0 + 1] : 0;
    int pair = c0 + c1;
    sh[t] = pair;
    __syncthreads();
    for (int off = 1; off < 512; off <<= 1) {
        int v = (t >= off) ? sh[t - off] : 0;
        __syncthreads();
        sh[t] += v;
        __syncthreads();
    }
    int ex = sh[t] - pair + base;
    if (i0 < NN) {
        g_rowstart[i0] = ex;
        g_fill[i0] = ex;
    }
    if (i0 + 1 < NN) {
        g_rowstart[i0 + 1] = ex + c0;
        g_fill[i0 + 1] = ex + c0;
    }
}

__global__ void fill_kernel(const int* __restrict__ ei) {
    int e = blockIdx.x * blockDim.x + threadIdx.x;
    if (e >= EE) return;
    int r = __ldg(&ei[e]);
    int c = __ldg(&ei[EE + e]);
    int pos = atomicAdd(&g_fill[c], 1);
    g_csr_r[pos] = r;
}

// ---------------- mm0: proven R13 compute, fp16 h output ----------------
#define MMB 256
#define MMG ((NN + MMB - 1) / MMB)      // 391
__global__ __launch_bounds__(128, 3) void mm0_kernel(const float* __restrict__ x,
                                                     const float* __restrict__ W) {
    __shared__ __align__(16) float Ws[FIN * HID];      // 32 KB
    __shared__ __align__(16) float xs[2][MMB * 16];    // 32 KB
    int tid = threadIdx.x;
    for (int i = tid; i < FIN * HID; i += 128) Ws[i] = W[i];

    int n0 = blockIdx.x * MMB;
    int lr = tid >> 2;
    int cb = tid & 3;

    auto issue_chunk = [&](int kc, int b) {
#pragma unroll
        for (int it = 0; it < 8; it++) {
            int r = it * 32 + lr;
            int gr = n0 + r;
            if (gr >= NN) gr = NN - 1;
            const float* src = &x[(size_t)gr * FIN + kc * 16 + cb * 4];
            int blk = cb ^ ((r >> 1) & 3);
            unsigned sdst = (unsigned)__cvta_generic_to_shared(&xs[b][r * 16 + blk * 4]);
            asm volatile("cp.async.cg.shared.global [%0], [%1], 16;"
                         :: "r"(sdst), "l"(src));
        }
        asm volatile("cp.async.commit_group;");
    };

    issue_chunk(0, 0);
    issue_chunk(1, 1);

    unsigned long long accA[8], accB[8];
#pragma unroll
    for (int p = 0; p < 8; p++) { accA[p] = 0ull; accB[p] = 0ull; }

    int r0 = tid;
    int r1 = tid + 128;
    int key = (tid >> 1) & 3;

    for (int kc = 0; kc < FIN / 16; kc++) {
        if (kc < FIN / 16 - 1)
            asm volatile("cp.async.wait_group 1;");
        else
            asm volatile("cp.async.wait_group 0;");
        __syncthreads();

        const float4* base = (const float4*)&xs[kc & 1][0];
#pragma unroll
        for (int c = 0; c < 4; c++) {
            float4 va = base[r0 * 4 + (c ^ key)];
            float4 vb = base[r1 * 4 + (c ^ key)];
            float xa[4] = {va.x, va.y, va.z, va.w};
            float xb[4] = {vb.x, vb.y, vb.z, vb.w};
#pragma unroll
            for (int kk = 0; kk < 4; kk++) {
                int k = kc * 16 + c * 4 + kk;
                const ulonglong2* wp = (const ulonglong2*)&Ws[k * HID];
                ulonglong2 w01 = wp[0], w23 = wp[1], w45 = wp[2], w67 = wp[3];
                unsigned long long xpA = pack2(xa[kk]);
                unsigned long long xpB = pack2(xb[kk]);
                fma2(accA[0], xpA, w01.x); fma2(accA[1], xpA, w01.y);
                fma2(accA[2], xpA, w23.x); fma2(accA[3], xpA, w23.y);
                fma2(accA[4], xpA, w45.x); fma2(accA[5], xpA, w45.y);
                fma2(accA[6], xpA, w67.x); fma2(accA[7], xpA, w67.y);
                fma2(accB[0], xpB, w01.x); fma2(accB[1], xpB, w01.y);
                fma2(accB[2], xpB, w23.x); fma2(accB[3], xpB, w23.y);
                fma2(accB[4], xpB, w45.x); fma2(accB[5], xpB, w45.y);
                fma2(accB[6], xpB, w67.x); fma2(accB[7], xpB, w67.y);
            }
        }
        __syncthreads();
        if (kc + 2 < FIN / 16) issue_chunk(kc + 2, kc & 1);
    }

    union { unsigned long long u; float2 f; } cv;
    int nA = n0 + r0;
    if (nA < NN) {
        float dv = g_deg[nA];
        __half2 h8[8];
#pragma unroll
        for (int q = 0; q < 8; q++) {
            cv.u = accA[q];
            h8[q] = __floats2half2_rn(cv.f.x * dv, cv.f.y * dv);
        }
        g_h[(size_t)nA * 2 + 0] = *(uint4*)&h8[0];
        g_h[(size_t)nA * 2 + 1] = *(uint4*)&h8[4];
    }
    int nB = n0 + r1;
    if (nB < NN) {
        float dv = g_deg[nB];
        __half2 h8[8];
#pragma unroll
        for (int q = 0; q < 8; q++) {
            cv.u = accB[q];
            h8[q] = __floats2half2_rn(cv.f.x * dv, cv.f.y * dv);
        }
        g_h[(size_t)nB * 2 + 0] = *(uint4*)&h8[0];
        g_h[(size_t)nB * 2 + 1] = *(uint4*)&h8[4];
    }
}

// ---------------- gather: warp per node, 4 lanes/edge (8B fp16 loads), 2-way unroll ----------------
__global__ __launch_bounds__(256) void gather_kernel() {
    int node = blockIdx.x * 8 + (threadIdx.x >> 5);
    if (node >= NN) return;
    int lane = threadIdx.x & 31;
    int p = lane & 3;

    int s = g_rowstart[node];
    int e = s + g_cnt[node];
    int j = s + (lane >> 2);

    float4 a0 = make_float4(0.f, 0.f, 0.f, 0.f);
    float4 a1 = make_float4(0.f, 0.f, 0.f, 0.f);
    const uint2* h2 = (const uint2*)g_h;   // 4 uint2 per node (4 halves each)

    while (j < e - 8) {
        int r0 = __ldg(&g_csr_r[j]);
        int r1 = __ldg(&g_csr_r[j + 8]);
        uint2 u0 = __ldg(&h2[(size_t)r0 * 4 + p]);
        uint2 u1 = __ldg(&h2[(size_t)r1 * 4 + p]);
        float2 f00 = __half22float2(*(__half2*)&u0.x);
        float2 f01 = __half22float2(*(__half2*)&u0.y);
        float2 f10 = __half22float2(*(__half2*)&u1.x);
        float2 f11 = __half22float2(*(__half2*)&u1.y);
        a0.x += f00.x; a0.y += f00.y; a0.z += f01.x; a0.w += f01.y;
        a1.x += f10.x; a1.y += f10.y; a1.z += f11.x; a1.w += f11.y;
        j += 16;
    }
    if (j < e) {
        int r0 = __ldg(&g_csr_r[j]);
        uint2 u0 = __ldg(&h2[(size_t)r0 * 4 + p]);
        float2 f00 = __half22float2(*(__half2*)&u0.x);
        float2 f01 = __half22float2(*(__half2*)&u0.y);
        a0.x += f00.x; a0.y += f00.y; a0.z += f01.x; a0.w += f01.y;
    }
    a0.x += a1.x; a0.y += a1.y; a0.z += a1.z; a0.w += a1.w;

#pragma unroll
    for (int m = 16; m >= 4; m >>= 1) {
        a0.x += __shfl_xor_sync(0xffffffff, a0.x, m);
        a0.y += __shfl_xor_sync(0xffffffff, a0.y, m);
        a0.z += __shfl_xor_sync(0xffffffff, a0.z, m);
        a0.w += __shfl_xor_sync(0xffffffff, a0.w, m);
    }
    if (lane < 4) {
        float dc = g_deg[node];
        a0.x *= dc; a0.y *= dc; a0.z *= dc; a0.w *= dc;
        ((float4*)g_agg)[(size_t)node * 4 + lane] = a0;
    }
}

// ---------------- fused stats + grid-sync + apply (+mm16 fp16-h / out fp32) ----------------
__global__ __launch_bounds__(256, 3) void statsapply_kernel(
    const float* __restrict__ L, const float* __restrict__ gamma,
    const float* __restrict__ beta, const float* __restrict__ Wn,
    float* __restrict__ out, int epoch, int isfinal)
{
    __shared__ float Ls[HID * NG];
    __shared__ float xs[256 * HID];
    __shared__ float ss[256 * NG];
    __shared__ float tsh[GF];
    __shared__ float rgS[GF];
    __shared__ float csS[HID];
    __shared__ float WsS[HID * HID];
    __shared__ int is_last;
    int tid = threadIdx.x;
    if (tid < HID * NG) Ls[tid] = L[tid];
    __syncthreads();

    int nIdx = blockIdx.x * 256 + tid;
    float xr[HID];
    float sv[NG];
#pragma unroll
    for (int k = 0; k < HID; k++) xr[k] = 0.0f;
#pragma unroll
    for (int g = 0; g < NG; g++) sv[g] = 0.0f;

    if (nIdx < NN) {
        const float4* xi = (const float4*)&g_agg[(size_t)nIdx * HID];
#pragma unroll
        for (int q = 0; q < 4; q++) {
            float4 v = xi[q];
            xr[q * 4 + 0] = v.x; xr[q * 4 + 1] = v.y; xr[q * 4 + 2] = v.z; xr[q * 4 + 3] = v.w;
        }
        float logit[NG];
#pragma unroll
        for (int g = 0; g < NG; g++) logit[g] = 0.0f;
#pragma unroll
        for (int k = 0; k < HID; k++)
#pragma unroll
            for (int g = 0; g < NG; g++) logit[g] += xr[k] * Ls[k * NG + g];
        float m = -CUDART_INF_F;
#pragma unroll
        for (int g = 0; g < NG; g++) m = fmaxf(m, logit[g]);
        float sum = 0.0f;
#pragma unroll
        for (int g = 0; g < NG; g++) { sv[g] = __expf(logit[g] - m); sum += sv[g]; }
        float inv = 1.0f / sum;
#pragma unroll
        for (int g = 0; g < NG; g++) sv[g] *= inv;
    }

    {
        float4* xw = (float4*)&xs[tid * HID];
#pragma unroll
        for (int q = 0; q < 4; q++)
            xw[q] = make_float4(xr[q * 4 + 0], xr[q * 4 + 1], xr[q * 4 + 2], xr[q * 4 + 3]);
#pragma unroll
        for (int g = 0; g < NG; g++) ss[tid * NG + g] = sv[g];
    }
    __syncthreads();

    if (tid < GF) {
        int g = tid >> 4;
        int f = tid & 15;
        float a1 = 0.0f, a2 = 0.0f;
        for (int jj = 0; jj < 256; jj++) {
            float t = ss[jj * NG + g] * xs[jj * HID + f];
            a1 += t;
            a2 += t * t;
        }
        atomicAdd(&g_sums[tid], (double)a1);
        atomicAdd(&g_sums[GF + tid], (double)a2);
    }

    __threadfence();
    if (tid == 0) {
        int old = atomicAdd(&g_ctr, 1);
        is_last = (old == (int)gridDim.x - 1) ? 1 : 0;
    }
    __syncthreads();
    if (is_last) {
        if (tid < GF) {
            double s1 = g_sums[tid];
            double s2 = g_sums[GF + tid];
            g_sums[tid] = 0.0;
            g_sums[GF + tid] = 0.0;
            double mean = s1 / (double)NN;
            double var  = s2 / (double)NN - mean * mean;
            float v = (float)var;
            if (v < 0.0f) v = 0.0f;
            float rs = rsqrtf(v + EPSN);
            float rg = rs * gamma[tid];
            g_rsg[tid] = rg;
            tsh[tid] = beta[tid] - (float)mean * rg;
        }
        __syncthreads();
        if (tid < HID) {
            float cf = 0.0f;
#pragma unroll
            for (int g = 0; g < NG; g++) cf += tsh[g * HID + tid];
            g_cvec[tid] = cf;
        }
        if (tid == 0) g_ctr = 0;
        __syncthreads();
        if (tid == 0) {
            __threadfence();
            atomicExch((int*)&g_flag, epoch);
        }
    }

    if (tid == 0) {
        while (atomicAdd((int*)&g_flag, 0) != epoch) __nanosleep(64);
    }
    __syncthreads();

    if (tid < GF) rgS[tid] = __ldcg(&g_rsg[tid]);
    if (tid < HID) csS[tid] = __ldcg(&g_cvec[tid]);
    if (!isfinal && tid < HID * HID) WsS[tid] = Wn[tid];
    __syncthreads();

    if (nIdx < NN) {
        float res[HID];
#pragma unroll
        for (int f = 0; f < HID; f++) {
            float a = 0.0f;
#pragma unroll
            for (int g = 0; g < NG; g++) a += sv[g] * rgS[g * HID + f];
            float v = xr[f] + LAMDA * (xr[f] * a + csS[f]);
            res[f] = fmaxf(v, 0.0f);
        }

        if (isfinal) {
            float4* o = (float4*)&out[(size_t)nIdx * HID];
#pragma unroll
            for (int q = 0; q < 4; q++)
                o[q] = make_float4(res[q * 4 + 0], res[q * 4 + 1],
                                   res[q * 4 + 2], res[q * 4 + 3]);
        } else {
            float acc[HID];
#pragma unroll
            for (int f = 0; f < HID; f++) acc[f] = 0.0f;
#pragma unroll
            for (int k = 0; k < HID; k++)
#pragma unroll
                for (int f = 0; f < HID; f++) acc[f] += res[k] * WsS[k * HID + f];
            float dv = g_deg[nIdx];
            __half2 h8[8];
#pragma unroll
            for (int q = 0; q < 8; q++)
                h8[q] = __floats2half2_rn(acc[2 * q] * dv, acc[2 * q + 1] * dv);
            g_h[(size_t)nIdx * 2 + 0] = *(uint4*)&h8[0];
            g_h[(size_t)nIdx * 2 + 1] = *(uint4*)&h8[4];
        }
    }

    // final layer: re-zero g_cnt for the next invocation / graph replay
    if (isfinal && nIdx < NN) g_cnt[nIdx] = 0;

    __threadfence();
    if (tid == 0) {
        int old = atomicAdd(&g_ctr2, 1);
        if (old == (int)gridDim.x - 1) {
            g_ctr2 = 0;
            atomicExch((int*)&g_flag, 0);
        }
    }
}

// ---------------- launcher ----------------
extern "C" void kernel_launch(void* const* d_in, const int* in_sizes, int n_in,
                              void* d_out, int out_size) {
    const float* x  = (const float*)d_in[0];
    const int*   ei = (const int*)d_in[1];
    const float* W[3] = {(const float*)d_in[2], (const float*)d_in[3], (const float*)d_in[4]};
    const float* L[3] = {(const float*)d_in[5], (const float*)d_in[6], (const float*)d_in[7]};
    const float* gm[3] = {(const float*)d_in[8], (const float*)d_in[9], (const float*)d_in[10]};
    const float* bt[3] = {(const float*)d_in[11], (const float*)d_in[12], (const float*)d_in[13]};
    float* out = (float*)d_out;

    const int TB = 256;
    count_kernel<<<(EE + TB - 1) / TB, TB>>>(ei);         // 1
    scan1_kernel<<<NBLK, 512>>>();                        // 2 (+dinv fused)
    mm0_kernel<<<MMG, 128>>>(x, W[0]);                    // 3
    scan3_kernel<<<NBLK, 512>>>();                        // 4
    fill_kernel<<<(EE + TB - 1) / TB, TB>>>(ei);          // 5

    for (int i = 0; i < 3; i++) {
        gather_kernel<<<(NN + 7) / 8, 256>>>();
        statsapply_kernel<<<(NN + 255) / 256, 256>>>(
            L[i], gm[i], bt[i], i < 2 ? W[i + 1] : W[0], out, i + 1, i == 2 ? 1 : 0);
    }
}